// round 15
// baseline (speedup 1.0000x reference)
#include <cuda_runtime.h>
#include <cuda_bf16.h>
#include <math.h>

#define BB 16
#define HH 480
#define WW 640
#define HW (HH*WW)
#define CC 256
#define HCC 60
#define WCC 80
#define KK 400
#define CAND_CAP 24576

#define CH 10               // output rows per block (best measured config)
#define NBY (HH / CH)       // 48
#define NT 160              // threads per block = 640/4 columns
#define SBUF 1024           // per-block candidate staging capacity

// output layout: kpts (16,400,2) | scores (16,400) | sampled (16,256,400) | heatmap (16,1,480,640)
#define OFF_KPTS 0
#define OFF_SCORES (BB*KK*2)
#define OFF_SAMPLED (OFF_SCORES + BB*KK)
#define OFF_HEAT (OFF_SAMPLED + BB*CC*KK)

__device__ unsigned int g_cval[BB*CAND_CAP];
__device__ unsigned int g_cidx[BB*CAND_CAP];
__device__ int g_count[BB];     // zero at load; reset in-kernel each replay
__device__ int g_done[BB];      // blocks-finished counter per batch; reset in-kernel
__device__ int g_topidx[BB*KK];

// Fused NMS + (last block per batch) exact top-K select.
// grid (NBY, BB), block 160. Thread = 4 consecutive columns (one float4).
__global__ __launch_bounds__(NT) void k_nms_select(const float* __restrict__ h,
                                                   float* __restrict__ out) {
    __shared__ unsigned int s_val[SBUF];
    __shared__ unsigned int s_idx[SBUF];
    __shared__ int s_cnt;
    __shared__ int s_base;
    __shared__ int s_last;
    // select-tail storage
    __shared__ unsigned int bins[2048];
    __shared__ int s_wsum[8];
    __shared__ unsigned int s_bin;
    __shared__ int s_newrank;
    __shared__ int s_fits;
    __shared__ unsigned long long s_keys[512];
    __shared__ int s_gcnt;

    int b   = blockIdx.y;
    int ty0 = blockIdx.x * CH;
    int tid = threadIdx.x;
    int lane = tid & 31, wid = tid >> 5;
    if (tid == 0) s_cnt = 0;
    __syncthreads();

    // ================= NMS phase =================
    {
        const float4* hb4 = reinterpret_cast<const float4*>(h + (size_t)b*HW);
        float4*       ob4 = reinterpret_cast<float4*>(out + OFF_HEAT + (size_t)b*HW);
        int xb = tid * 4;

        float4 zero4 = make_float4(0.f, 0.f, 0.f, 0.f);
        float4 w0=zero4,w1=zero4,w2=zero4,w3=zero4,w4=zero4,w5=zero4,w6=zero4;
        float4 d0=zero4,d1=zero4,d2=zero4;

        #pragma unroll
        for (int t = 0; t < CH + 6; ++t) {
            int yy = ty0 - 3 + t;
            float4 qm = zero4, qc = zero4, qp = zero4;
            if (yy >= 0 && yy < HH) {
                int rb = yy * (WW/4);
                qc = __ldg(hb4 + rb + tid);
                if (tid > 0)      qm = __ldg(hb4 + rb + tid - 1);
                if (tid < NT - 1) qp = __ldg(hb4 + rb + tid + 1);
                if (t >= 3 && t < CH + 3) ob4[rb + tid] = qc;
            }
            float p1 = fmaxf(qm.y, qm.z);
            float p2 = fmaxf(qm.z, qm.w);
            float p3 = fmaxf(qm.w, qc.x);
            float p4 = fmaxf(qc.x, qc.y);
            float p5 = fmaxf(qc.y, qc.z);
            float p6 = fmaxf(qc.z, qc.w);
            float p7 = fmaxf(qc.w, qp.x);
            float p8 = fmaxf(qp.x, qp.y);
            float4 rm;
            rm.x = fmaxf(fmaxf(p1, p3), fmaxf(p5, qc.w));
            rm.y = fmaxf(fmaxf(p2, p4), fmaxf(p6, qp.x));
            rm.z = fmaxf(fmaxf(p3, p5), fmaxf(p7, qp.y));
            rm.w = fmaxf(fmaxf(p4, p6), fmaxf(p8, qp.z));

            float4 vcand = d0;
            d0 = d1; d1 = d2; d2 = qc;
            w0 = w1; w1 = w2; w2 = w3; w3 = w4; w4 = w5; w5 = w6; w6 = rm;

            if (t >= 6) {
                int yc = yy - 3;
                if (yc >= 4 && yc < HH - 4) {
                    float4 m;
                    m.x = fmaxf(fmaxf(fmaxf(w0.x,w1.x),fmaxf(w2.x,w3.x)),
                                fmaxf(fmaxf(w4.x,w5.x),w6.x));
                    m.y = fmaxf(fmaxf(fmaxf(w0.y,w1.y),fmaxf(w2.y,w3.y)),
                                fmaxf(fmaxf(w4.y,w5.y),w6.y));
                    m.z = fmaxf(fmaxf(fmaxf(w0.z,w1.z),fmaxf(w2.z,w3.z)),
                                fmaxf(fmaxf(w4.z,w5.z),w6.z));
                    m.w = fmaxf(fmaxf(fmaxf(w0.w,w1.w),fmaxf(w2.w,w3.w)),
                                fmaxf(fmaxf(w4.w,w5.w),w6.w));
                    float vj[4] = {vcand.x, vcand.y, vcand.z, vcand.w};
                    float mj[4] = {m.x, m.y, m.z, m.w};
                    #pragma unroll
                    for (int j = 0; j < 4; ++j) {
                        int x = tid*4 + j;
                        (void)xb;
                        if (x >= 4 && x < WW-4 && vj[j] > 0.f && vj[j] >= mj[j]) {
                            int p = atomicAdd(&s_cnt, 1);
                            if (p < SBUF) {
                                s_val[p] = 0xFFFFFFFFu - __float_as_uint(vj[j]);
                                s_idx[p] = (unsigned)(yc*WW + x);
                            }
                        }
                    }
                }
            }
        }

        __syncthreads();
        int cnt = s_cnt; if (cnt > SBUF) cnt = SBUF;
        if (tid == 0) s_base = atomicAdd(&g_count[b], cnt);
        __syncthreads();
        int base = s_base;
        for (int i = tid; i < cnt; i += NT) {
            int slot = base + i;
            if (slot < CAND_CAP) {
                g_cval[b*CAND_CAP + slot] = s_val[i];
                g_cidx[b*CAND_CAP + slot] = s_idx[i];
            }
        }
    }

    // ============== last-block handoff ==============
    __threadfence();
    __syncthreads();
    if (tid == 0) {
        int done = atomicAdd(&g_done[b], 1);
        s_last = (done == NBY - 1) ? 1 : 0;
    }
    __syncthreads();
    if (!s_last) return;

    // ================= SELECT phase (one block per batch) =================
    int n = g_count[b]; if (n > CAND_CAP) n = CAND_CAP;
    const unsigned int* vals = g_cval + (size_t)b*CAND_CAP;
    const unsigned int* idxs = g_cidx + (size_t)b*CAND_CAP;

    int nIter = (n + NT - 1) / NT;
    int gshift = 21;
    unsigned int gpiv = 2047u;           // n < KK: take everything
    int rank = KK;

    if (n >= KK) {
        // ---- pass 1: 2048 bins over vk[31:21] ----
        for (int i = tid; i < 2048; i += NT) bins[i] = 0;
        __syncthreads();
        for (int it = 0; it < nIter; ++it) {
            int i = it*NT + tid;
            bool active = (i < n);
            unsigned int vk = active ? vals[i] : 0u;
            unsigned int bin = vk >> 21;
            unsigned int mm = __ballot_sync(0xFFFFFFFFu, active);
            if (active) {
                unsigned int peers = __match_any_sync(mm, bin);
                int ldr = __ffs(peers) - 1;
                if (lane == ldr) atomicAdd(&bins[bin], (unsigned)__popc(peers));
            }
        }
        __syncthreads();

        // scan: threads 0..127 own 16 bins each
        {
            int lsum = 0;
            if (tid < 128) {
                #pragma unroll
                for (int j = 0; j < 16; ++j) lsum += (int)bins[tid*16 + j];
            }
            int v2 = lsum;
            #pragma unroll
            for (int o = 1; o < 32; o <<= 1) {
                int t = __shfl_up_sync(0xFFFFFFFFu, v2, o);
                if (lane >= o) v2 += t;
            }
            if (tid < 128 && lane == 31) s_wsum[wid] = v2;
            __syncthreads();
            int woff = 0;
            if (tid < 128) for (int w = 0; w < wid; ++w) woff += s_wsum[w];
            int incl = v2 + woff;
            int excl = incl - lsum;
            if (tid < 128 && rank > excl && rank <= incl) {
                int acc = excl;
                for (int j = 0; j < 16; ++j) {
                    int cb = (int)bins[tid*16 + j];
                    if (rank <= acc + cb) {
                        s_bin = (unsigned)(tid*16 + j);
                        s_newrank = rank - acc;
                        s_fits = (acc + cb <= 512) ? 1 : 0;
                        break;
                    }
                    acc += cb;
                }
            }
            __syncthreads();
        }
        unsigned int coarse = s_bin;
        rank = s_newrank;
        int fits = s_fits;
        __syncthreads();

        if (fits) {
            gshift = 21; gpiv = coarse;
        } else {
            // ---- pass 2 (rare): refine within coarse bin over vk[20:10] ----
            for (int i = tid; i < 2048; i += NT) bins[i] = 0;
            __syncthreads();
            for (int it = 0; it < nIter; ++it) {
                int i = it*NT + tid;
                bool active = (i < n);
                unsigned int vk = active ? vals[i] : 0u;
                bool ok = active && ((vk >> 21) == coarse);
                unsigned int bin = (vk >> 10) & 2047u;
                unsigned int mm = __ballot_sync(0xFFFFFFFFu, ok);
                if (ok) {
                    unsigned int peers = __match_any_sync(mm, bin);
                    int ldr = __ffs(peers) - 1;
                    if (lane == ldr) atomicAdd(&bins[bin], (unsigned)__popc(peers));
                }
            }
            __syncthreads();
            {
                int lsum = 0;
                if (tid < 128) {
                    #pragma unroll
                    for (int j = 0; j < 16; ++j) lsum += (int)bins[tid*16 + j];
                }
                int v2 = lsum;
                #pragma unroll
                for (int o = 1; o < 32; o <<= 1) {
                    int t = __shfl_up_sync(0xFFFFFFFFu, v2, o);
                    if (lane >= o) v2 += t;
                }
                if (tid < 128 && lane == 31) s_wsum[wid] = v2;
                __syncthreads();
                int woff = 0;
                if (tid < 128) for (int w = 0; w < wid; ++w) woff += s_wsum[w];
                int incl = v2 + woff;
                int excl = incl - lsum;
                if (tid < 128 && rank > excl && rank <= incl) {
                    int acc = excl;
                    for (int j = 0; j < 16; ++j) {
                        int cb = (int)bins[tid*16 + j];
                        if (rank <= acc + cb) { s_bin = (unsigned)(tid*16 + j); break; }
                        acc += cb;
                    }
                }
                __syncthreads();
            }
            gshift = 10; gpiv = (coarse << 11) | s_bin;
            __syncthreads();
        }
    }

    // single-pass gather: (vk >> gshift) <= gpiv
    if (tid == 0) s_gcnt = 0;
    __syncthreads();
    for (int it = 0; it < nIter; ++it) {
        int i = it*NT + tid;
        bool active = (i < n);
        unsigned int vk = active ? vals[i] : 0xFFFFFFFFu;
        bool take = active && ((vk >> gshift) <= gpiv);
        unsigned int mm = __ballot_sync(0xFFFFFFFFu, take);
        if (take) {
            int ldr = __ffs(mm) - 1;
            int base;
            if (lane == ldr) base = atomicAdd(&s_gcnt, __popc(mm));
            base = __shfl_sync(mm, base, ldr);
            int slot = base + __popc(mm & ((1u << lane) - 1u));
            if (slot < 512)
                s_keys[slot] = ((unsigned long long)vk << 32) | idxs[i];
        }
    }
    __syncthreads();
    int gcnt = s_gcnt; if (gcnt > 512) gcnt = 512;
    for (int i = tid; i < 512; i += NT)
        if (i >= gcnt) s_keys[i] = ~0ULL;
    __syncthreads();

    // bitonic sort 512 ascending on (value,idx)
    for (unsigned kk2 = 2; kk2 <= 512; kk2 <<= 1) {
        for (unsigned j = kk2 >> 1; j > 0; j >>= 1) {
            for (unsigned i = tid; i < 512; i += NT) {
                unsigned ixj = i ^ j;
                if (ixj > i) {
                    bool asc = ((i & kk2) == 0);
                    unsigned long long a = s_keys[i], c = s_keys[ixj];
                    if ((a > c) == asc) { s_keys[i] = c; s_keys[ixj] = a; }
                }
            }
            __syncthreads();
        }
    }

    for (int k = tid; k < KK; k += NT) {
        unsigned long long key = s_keys[k];
        unsigned int vb = 0xFFFFFFFFu - (unsigned int)(key >> 32);
        int idx = (int)(unsigned int)(key & 0xFFFFFFFFu);
        int y = idx / WW;
        int x = idx - y*WW;
        out[OFF_KPTS + ((size_t)b*KK + k)*2 + 0] = (float)x + 0.5f;
        out[OFF_KPTS + ((size_t)b*KK + k)*2 + 1] = (float)y + 0.5f;
        out[OFF_SCORES + (size_t)b*KK + k] = __uint_as_float(vb);
        g_topidx[b*KK + k] = idx;
    }

    // reset per-batch state for next graph replay
    if (tid == 0) { g_count[b] = 0; g_done[b] = 0; }
}

// bilinear descriptor sample + L2 norm. grid (KK/8, BB), block 256 (thread = channel).
// float4 corner gather + contiguous float4 output writes. (R7-proven form.)
__global__ __launch_bounds__(256) void k_sample(const float* __restrict__ desc,
                                                float* __restrict__ out) {
    __shared__ int   s_a0[8];
    __shared__ int   s_a1[8];
    __shared__ int   s_sh[8];
    __shared__ float s_wq[8][4];
    __shared__ float s_norm[8];
    __shared__ float s_inv[8];

    int b  = blockIdx.y;
    int k0 = blockIdx.x * 8;
    int c  = threadIdx.x;
    int lane = c & 31;

    if (c < 8) {
        int idx = g_topidx[b*KK + k0 + c];
        int iy = idx / WW;
        int ix = idx - iy*WW;
        float kx = (float)ix + 0.5f;
        float ky = (float)iy + 0.5f;
        float ux = (kx - 3.5f) / 635.5f;
        float uy = (ky - 3.5f) / 475.5f;
        float gx = ((ux * 2.f - 1.f) + 1.f) * 0.5f * (float)(WCC - 1);
        float gy = ((uy * 2.f - 1.f) + 1.f) * 0.5f * (float)(HCC - 1);
        float x0f = floorf(gx), y0f = floorf(gy);
        float wx = gx - x0f, wy = gy - y0f;
        int x0 = (int)x0f;
        int y0 = (int)y0f;
        int off0 = y0*WCC + x0;
        int off1 = (y0+1)*WCC + x0;
        s_sh[c] = x0 & 3;
        s_a0[c] = off0 >> 2;
        s_a1[c] = off1 >> 2;
        s_wq[c][0] = (1.f - wx) * (1.f - wy);
        s_wq[c][1] = wx * (1.f - wy);
        s_wq[c][2] = (1.f - wx) * wy;
        s_wq[c][3] = wx * wy;
        s_norm[c] = 0.f;
    }
    __syncthreads();

    const float*  dp = desc + ((size_t)b*CC + c) * (HCC*WCC);
    const float4* d4 = reinterpret_cast<const float4*>(dp);

    float vv[8];
    #pragma unroll
    for (int kk = 0; kk < 8; ++kk) {
        int a0 = s_a0[kk], a1 = s_a1[kk], sh = s_sh[kk];
        float4 q0 = __ldg(d4 + a0);
        float4 q1 = __ldg(d4 + a1);
        float e00, e01, e10, e11;
        if (sh == 0)      { e00 = q0.x; e01 = q0.y; e10 = q1.x; e11 = q1.y; }
        else if (sh == 1) { e00 = q0.y; e01 = q0.z; e10 = q1.y; e11 = q1.z; }
        else if (sh == 2) { e00 = q0.z; e01 = q0.w; e10 = q1.z; e11 = q1.w; }
        else {
            e00 = q0.w; e10 = q1.w;
            e01 = __ldg(dp + a0*4 + 4);
            e11 = __ldg(dp + a1*4 + 4);
        }
        float v = e00*s_wq[kk][0] + e01*s_wq[kk][1]
                + e10*s_wq[kk][2] + e11*s_wq[kk][3];
        vv[kk] = v;
        float s = v * v;
        #pragma unroll
        for (int o = 16; o > 0; o >>= 1) s += __shfl_xor_sync(0xFFFFFFFFu, s, o);
        if (lane == 0) atomicAdd(&s_norm[kk], s);
    }
    __syncthreads();
    if (c < 8) s_inv[c] = 1.0f / sqrtf(s_norm[c] + 1e-12f);
    __syncthreads();

    float4 o0, o1;
    o0.x = vv[0]*s_inv[0]; o0.y = vv[1]*s_inv[1];
    o0.z = vv[2]*s_inv[2]; o0.w = vv[3]*s_inv[3];
    o1.x = vv[4]*s_inv[4]; o1.y = vv[5]*s_inv[5];
    o1.z = vv[6]*s_inv[6]; o1.w = vv[7]*s_inv[7];
    float4* op = reinterpret_cast<float4*>(out + OFF_SAMPLED + ((size_t)b*CC + c)*KK + k0);
    op[0] = o0;
    op[1] = o1;
}

extern "C" void kernel_launch(void* const* d_in, const int* in_sizes, int n_in,
                              void* d_out, int out_size) {
    const float* heat = (const float*)d_in[0];
    const float* desc = (const float*)d_in[1];
    float* out = (float*)d_out;

    dim3 ngrid(NBY, BB);
    k_nms_select<<<ngrid, NT>>>(heat, out);

    dim3 sgrid(KK / 8, BB);
    k_sample<<<sgrid, 256>>>(desc, out);
}

// round 16
// speedup vs baseline: 1.7782x; 1.7782x over previous
#include <cuda_runtime.h>
#include <cuda_bf16.h>
#include <math.h>

#define BB 16
#define HH 480
#define WW 640
#define HW (HH*WW)
#define CC 256
#define HCC 60
#define WCC 80
#define KK 400
#define CAND_CAP 24576

#define CH 10               // output rows per block (best measured config)
#define NBY (HH / CH)       // 48
#define NT 160              // threads per block = 640/4 columns
#define SBUF 1024           // per-block candidate staging capacity

// output layout: kpts (16,400,2) | scores (16,400) | sampled (16,256,400) | heatmap (16,1,480,640)
#define OFF_KPTS 0
#define OFF_SCORES (BB*KK*2)
#define OFF_SAMPLED (OFF_SCORES + BB*KK)
#define OFF_HEAT (OFF_SAMPLED + BB*CC*KK)

__device__ unsigned int g_cval[BB*CAND_CAP];
__device__ unsigned int g_cidx[BB*CAND_CAP];
__device__ int g_count[BB];      // zero at load; re-zeroed by k_select tail each replay
__device__ int g_topidx[BB*KK];
__device__ float g_norm[BB*KK];  // per-(b,k) sum of v^2; zeroed by k_select tail

// Fused NMS: heatmap copy + separable 7x7 max + compaction. (R7-proven form.)
__global__ __launch_bounds__(NT) void k_nms(const float* __restrict__ h,
                                            float* __restrict__ out) {
    __shared__ unsigned int s_val[SBUF];
    __shared__ unsigned int s_idx[SBUF];
    __shared__ int s_cnt;
    __shared__ int s_base;

    int b   = blockIdx.y;
    int ty0 = blockIdx.x * CH;
    int tid = threadIdx.x;
    if (tid == 0) s_cnt = 0;
    __syncthreads();

    const float4* hb4 = reinterpret_cast<const float4*>(h + (size_t)b*HW);
    float4*       ob4 = reinterpret_cast<float4*>(out + OFF_HEAT + (size_t)b*HW);
    int xb = tid * 4;

    float4 zero4 = make_float4(0.f, 0.f, 0.f, 0.f);
    float4 w0=zero4,w1=zero4,w2=zero4,w3=zero4,w4=zero4,w5=zero4,w6=zero4;
    float4 d0=zero4,d1=zero4,d2=zero4;

    #pragma unroll
    for (int t = 0; t < CH + 6; ++t) {
        int yy = ty0 - 3 + t;
        float4 qm = zero4, qc = zero4, qp = zero4;
        if (yy >= 0 && yy < HH) {
            int rb = yy * (WW/4);
            qc = __ldg(hb4 + rb + tid);
            if (tid > 0)      qm = __ldg(hb4 + rb + tid - 1);
            if (tid < NT - 1) qp = __ldg(hb4 + rb + tid + 1);
            if (t >= 3 && t < CH + 3) ob4[rb + tid] = qc;
        }
        float p1 = fmaxf(qm.y, qm.z);
        float p2 = fmaxf(qm.z, qm.w);
        float p3 = fmaxf(qm.w, qc.x);
        float p4 = fmaxf(qc.x, qc.y);
        float p5 = fmaxf(qc.y, qc.z);
        float p6 = fmaxf(qc.z, qc.w);
        float p7 = fmaxf(qc.w, qp.x);
        float p8 = fmaxf(qp.x, qp.y);
        float4 rm;
        rm.x = fmaxf(fmaxf(p1, p3), fmaxf(p5, qc.w));
        rm.y = fmaxf(fmaxf(p2, p4), fmaxf(p6, qp.x));
        rm.z = fmaxf(fmaxf(p3, p5), fmaxf(p7, qp.y));
        rm.w = fmaxf(fmaxf(p4, p6), fmaxf(p8, qp.z));

        float4 vcand = d0;
        d0 = d1; d1 = d2; d2 = qc;
        w0 = w1; w1 = w2; w2 = w3; w3 = w4; w4 = w5; w5 = w6; w6 = rm;

        if (t >= 6) {
            int yc = yy - 3;
            if (yc >= 4 && yc < HH - 4) {
                float4 m;
                m.x = fmaxf(fmaxf(fmaxf(w0.x,w1.x),fmaxf(w2.x,w3.x)),
                            fmaxf(fmaxf(w4.x,w5.x),w6.x));
                m.y = fmaxf(fmaxf(fmaxf(w0.y,w1.y),fmaxf(w2.y,w3.y)),
                            fmaxf(fmaxf(w4.y,w5.y),w6.y));
                m.z = fmaxf(fmaxf(fmaxf(w0.z,w1.z),fmaxf(w2.z,w3.z)),
                            fmaxf(fmaxf(w4.z,w5.z),w6.z));
                m.w = fmaxf(fmaxf(fmaxf(w0.w,w1.w),fmaxf(w2.w,w3.w)),
                            fmaxf(fmaxf(w4.w,w5.w),w6.w));
                float vj[4] = {vcand.x, vcand.y, vcand.z, vcand.w};
                float mj[4] = {m.x, m.y, m.z, m.w};
                #pragma unroll
                for (int j = 0; j < 4; ++j) {
                    int x = xb + j;
                    if (x >= 4 && x < WW-4 && vj[j] > 0.f && vj[j] >= mj[j]) {
                        int p = atomicAdd(&s_cnt, 1);
                        if (p < SBUF) {
                            s_val[p] = 0xFFFFFFFFu - __float_as_uint(vj[j]);
                            s_idx[p] = (unsigned)(yc*WW + x);
                        }
                    }
                }
            }
        }
    }

    __syncthreads();
    int cnt = s_cnt; if (cnt > SBUF) cnt = SBUF;
    if (tid == 0) s_base = atomicAdd(&g_count[b], cnt);
    __syncthreads();
    int base = s_base;
    for (int i = tid; i < cnt; i += NT) {
        int slot = base + i;
        if (slot < CAND_CAP) {
            g_cval[b*CAND_CAP + slot] = s_val[i];
            g_cidx[b*CAND_CAP + slot] = s_idx[i];
        }
    }
}

// exact per-batch top-K (R13-proven): one 2048-bin histogram; direct gather
// when the coarse set fits 512, else one refine pass. Bitonic sort.
__global__ __launch_bounds__(1024) void k_select(float* __restrict__ out) {
    __shared__ unsigned int bins[2048];
    __shared__ int s_warp[32];
    __shared__ unsigned int s_bin;
    __shared__ int s_newrank;
    __shared__ int s_fits;
    __shared__ unsigned long long s_keys[512];
    __shared__ int s_cnt;

    int b = blockIdx.x;
    int tid = threadIdx.x;
    int lane = tid & 31, wid = tid >> 5;
    int n = g_count[b]; if (n > CAND_CAP) n = CAND_CAP;
    const unsigned int* vals = g_cval + (size_t)b*CAND_CAP;
    const unsigned int* idxs = g_cidx + (size_t)b*CAND_CAP;

    int nIter = (n + 1023) >> 10;
    int gshift = 21;
    unsigned int gpiv = 2047u;
    int rank = KK;

    if (n >= KK) {
        for (int i = tid; i < 2048; i += 1024) bins[i] = 0;
        __syncthreads();
        for (int it = 0; it < nIter; ++it) {
            int i = (it << 10) + tid;
            bool active = (i < n);
            unsigned int vk = active ? vals[i] : 0u;
            unsigned int bin = vk >> 21;
            unsigned int m = __ballot_sync(0xFFFFFFFFu, active);
            if (active) {
                unsigned int peers = __match_any_sync(m, bin);
                int ldr = __ffs(peers) - 1;
                if (lane == ldr) atomicAdd(&bins[bin], (unsigned)__popc(peers));
            }
        }
        __syncthreads();
        {
            int c0 = (int)bins[2*tid];
            int c1 = (int)bins[2*tid + 1];
            int s = c0 + c1;
            int v2 = s;
            #pragma unroll
            for (int o = 1; o < 32; o <<= 1) {
                int t = __shfl_up_sync(0xFFFFFFFFu, v2, o);
                if (lane >= o) v2 += t;
            }
            if (lane == 31) s_warp[wid] = v2;
            __syncthreads();
            if (wid == 0) {
                int ws = s_warp[lane];
                #pragma unroll
                for (int o = 1; o < 32; o <<= 1) {
                    int t = __shfl_up_sync(0xFFFFFFFFu, ws, o);
                    if (lane >= o) ws += t;
                }
                s_warp[lane] = ws;
            }
            __syncthreads();
            int incl = v2 + (wid > 0 ? s_warp[wid - 1] : 0);
            int excl = incl - s;
            if (rank > excl && rank <= excl + c0) {
                s_bin = (unsigned)(2*tid);
                s_newrank = rank - excl;
                s_fits = (excl + c0 <= 512);
            } else if (rank > excl + c0 && rank <= incl) {
                s_bin = (unsigned)(2*tid + 1);
                s_newrank = rank - excl - c0;
                s_fits = (excl + c0 + c1 <= 512);
            }
            __syncthreads();
        }
        unsigned int coarse = s_bin;
        rank = s_newrank;
        int fits = s_fits;
        __syncthreads();

        if (fits) {
            gshift = 21; gpiv = coarse;
        } else {
            for (int i = tid; i < 2048; i += 1024) bins[i] = 0;
            __syncthreads();
            for (int it = 0; it < nIter; ++it) {
                int i = (it << 10) + tid;
                bool active = (i < n);
                unsigned int vk = active ? vals[i] : 0u;
                bool ok = active && ((vk >> 21) == coarse);
                unsigned int bin = (vk >> 10) & 2047u;
                unsigned int m = __ballot_sync(0xFFFFFFFFu, ok);
                if (ok) {
                    unsigned int peers = __match_any_sync(m, bin);
                    int ldr = __ffs(peers) - 1;
                    if (lane == ldr) atomicAdd(&bins[bin], (unsigned)__popc(peers));
                }
            }
            __syncthreads();
            {
                int d0 = (int)bins[2*tid];
                int d1 = (int)bins[2*tid + 1];
                int ss = d0 + d1;
                int vv2 = ss;
                #pragma unroll
                for (int o = 1; o < 32; o <<= 1) {
                    int t = __shfl_up_sync(0xFFFFFFFFu, vv2, o);
                    if (lane >= o) vv2 += t;
                }
                if (lane == 31) s_warp[wid] = vv2;
                __syncthreads();
                if (wid == 0) {
                    int ws = s_warp[lane];
                    #pragma unroll
                    for (int o = 1; o < 32; o <<= 1) {
                        int t = __shfl_up_sync(0xFFFFFFFFu, ws, o);
                        if (lane >= o) ws += t;
                    }
                    s_warp[lane] = ws;
                }
                __syncthreads();
                int incl2 = vv2 + (wid > 0 ? s_warp[wid - 1] : 0);
                int excl2 = incl2 - ss;
                if (rank > excl2 && rank <= excl2 + d0)
                    s_bin = (unsigned)(2*tid);
                else if (rank > excl2 + d0 && rank <= incl2)
                    s_bin = (unsigned)(2*tid + 1);
                __syncthreads();
            }
            gshift = 10; gpiv = (coarse << 11) | s_bin;
            __syncthreads();
        }
    }

    if (tid == 0) s_cnt = 0;
    __syncthreads();
    for (int it = 0; it < nIter; ++it) {
        int i = (it << 10) + tid;
        bool active = (i < n);
        unsigned int vk = active ? vals[i] : 0xFFFFFFFFu;
        bool take = active && ((vk >> gshift) <= gpiv);
        unsigned int m = __ballot_sync(0xFFFFFFFFu, take);
        if (take) {
            int ldr = __ffs(m) - 1;
            int base;
            if (lane == ldr) base = atomicAdd(&s_cnt, __popc(m));
            base = __shfl_sync(m, base, ldr);
            int slot = base + __popc(m & ((1u << lane) - 1u));
            if (slot < 512)
                s_keys[slot] = ((unsigned long long)vk << 32) | idxs[i];
        }
    }
    __syncthreads();
    int cnt = s_cnt; if (cnt > 512) cnt = 512;
    for (int i = tid; i < 512; i += 1024)
        if (i >= cnt) s_keys[i] = ~0ULL;
    __syncthreads();

    for (unsigned kk2 = 2; kk2 <= 512; kk2 <<= 1) {
        for (unsigned j = kk2 >> 1; j > 0; j >>= 1) {
            for (unsigned i = tid; i < 512; i += 1024) {
                unsigned ixj = i ^ j;
                if (ixj > i) {
                    bool asc = ((i & kk2) == 0);
                    unsigned long long a = s_keys[i], c = s_keys[ixj];
                    if ((a > c) == asc) { s_keys[i] = c; s_keys[ixj] = a; }
                }
            }
            __syncthreads();
        }
    }

    for (int k = tid; k < KK; k += 1024) {
        unsigned long long key = s_keys[k];
        unsigned int vb = 0xFFFFFFFFu - (unsigned int)(key >> 32);
        int idx = (int)(unsigned int)(key & 0xFFFFFFFFu);
        int y = idx / WW;
        int x = idx - y*WW;
        out[OFF_KPTS + ((size_t)b*KK + k)*2 + 0] = (float)x + 0.5f;
        out[OFF_KPTS + ((size_t)b*KK + k)*2 + 1] = (float)y + 0.5f;
        out[OFF_SCORES + (size_t)b*KK + k] = __uint_as_float(vb);
        g_topidx[b*KK + k] = idx;
    }

    // reset for next replay: count + norm accumulators (before k_gather runs)
    if (tid == 0) g_count[b] = 0;
    for (int k = tid; k < KK; k += 1024) g_norm[b*KK + k] = 0.f;
}

// Phase A: channel-resident sampling. One block per (channel, batch).
// Coalesced float4 load of the whole 60x80 channel into smem, then all 400
// keypoints sampled from smem (coalesced k-contiguous stores), norm partials
// accumulated via one spread-address global atomic per (block,kpt).
__global__ __launch_bounds__(256) void k_gather(const float* __restrict__ desc,
                                                float* __restrict__ out) {
    __shared__ float s_ch[HCC*WCC];   // 4800 floats = 19200 B

    int c = blockIdx.x;
    int b = blockIdx.y;
    int tid = threadIdx.x;

    const float4* dp4 = reinterpret_cast<const float4*>(
        desc + ((size_t)b*CC + c) * (HCC*WCC));
    float4* s4 = reinterpret_cast<float4*>(s_ch);
    #pragma unroll
    for (int i = tid; i < (HCC*WCC)/4; i += 256)   // 1200 float4
        s4[i] = __ldg(dp4 + i);
    __syncthreads();

    float* orow = out + OFF_SAMPLED + ((size_t)b*CC + c) * KK;
    const int* tix = g_topidx + b*KK;

    for (int k = tid; k < KK; k += 256) {
        int idx = __ldg(tix + k);
        int iy = idx / WW;
        int ix = idx - iy*WW;
        float kx = (float)ix + 0.5f;
        float ky = (float)iy + 0.5f;
        float ux = (kx - 3.5f) / 635.5f;
        float uy = (ky - 3.5f) / 475.5f;
        float gx = ((ux * 2.f - 1.f) + 1.f) * 0.5f * (float)(WCC - 1);
        float gy = ((uy * 2.f - 1.f) + 1.f) * 0.5f * (float)(HCC - 1);
        float x0f = floorf(gx), y0f = floorf(gy);
        float wx = gx - x0f, wy = gy - y0f;
        int x0 = (int)x0f;              // in [0,78]; x1=x0+1 never clamped
        int y0 = (int)y0f;              // in [0,58]; y1=y0+1 never clamped
        int o0 = y0*WCC + x0;
        int o1 = o0 + WCC;
        float d00 = s_ch[o0],     d01 = s_ch[o0 + 1];
        float d10 = s_ch[o1],     d11 = s_ch[o1 + 1];
        float v = d00*(1.f-wx)*(1.f-wy) + d01*wx*(1.f-wy)
                + d10*(1.f-wx)*wy       + d11*wx*wy;
        orow[k] = v;
        atomicAdd(&g_norm[b*KK + k], v*v);
    }
}

// Phase C: in-place normalize. grid (KK/8, BB), block 256 (thread = channel).
__global__ __launch_bounds__(256) void k_scale(float* __restrict__ out) {
    __shared__ float s_inv[8];
    int b  = blockIdx.y;
    int k0 = blockIdx.x * 8;
    int c  = threadIdx.x;
    if (c < 8) s_inv[c] = 1.0f / sqrtf(g_norm[b*KK + k0 + c] + 1e-12f);
    __syncthreads();
    float4* op = reinterpret_cast<float4*>(out + OFF_SAMPLED + ((size_t)b*CC + c)*KK + k0);
    float4 o0 = op[0], o1 = op[1];
    o0.x *= s_inv[0]; o0.y *= s_inv[1]; o0.z *= s_inv[2]; o0.w *= s_inv[3];
    o1.x *= s_inv[4]; o1.y *= s_inv[5]; o1.z *= s_inv[6]; o1.w *= s_inv[7];
    op[0] = o0;
    op[1] = o1;
}

extern "C" void kernel_launch(void* const* d_in, const int* in_sizes, int n_in,
                              void* d_out, int out_size) {
    const float* heat = (const float*)d_in[0];
    const float* desc = (const float*)d_in[1];
    float* out = (float*)d_out;

    dim3 ngrid(NBY, BB);
    k_nms<<<ngrid, NT>>>(heat, out);

    k_select<<<BB, 1024>>>(out);

    dim3 ggrid(CC, BB);
    k_gather<<<ggrid, 256>>>(desc, out);

    dim3 sgrid(KK / 8, BB);
    k_scale<<<sgrid, 256>>>(out);
}

// round 17
// speedup vs baseline: 1.8904x; 1.0631x over previous
#include <cuda_runtime.h>
#include <cuda_bf16.h>
#include <math.h>

#define BB 16
#define HH 480
#define WW 640
#define HW (HH*WW)
#define CC 256
#define HCC 60
#define WCC 80
#define KK 400
#define CAND_CAP 24576

#define CH 10               // output rows per block (best measured config)
#define NBY (HH / CH)       // 48
#define NT 160              // threads per block = 640/4 columns
#define SBUF 1024           // per-block candidate staging capacity

#define KT 16               // kpts per norm/scale tile
#define NKT (KK / KT)       // 25

// output layout: kpts (16,400,2) | scores (16,400) | sampled (16,256,400) | heatmap (16,1,480,640)
#define OFF_KPTS 0
#define OFF_SCORES (BB*KK*2)
#define OFF_SAMPLED (OFF_SCORES + BB*KK)
#define OFF_HEAT (OFF_SAMPLED + BB*CC*KK)

__device__ unsigned int g_cval[BB*CAND_CAP];
__device__ unsigned int g_cidx[BB*CAND_CAP];
__device__ int g_count[BB];      // zero at load; re-zeroed by k_select tail each replay
__device__ int g_topidx[BB*KK];

// Fused NMS: heatmap copy + separable 7x7 max + compaction. (proven form)
__global__ __launch_bounds__(NT) void k_nms(const float* __restrict__ h,
                                            float* __restrict__ out) {
    __shared__ unsigned int s_val[SBUF];
    __shared__ unsigned int s_idx[SBUF];
    __shared__ int s_cnt;
    __shared__ int s_base;

    int b   = blockIdx.y;
    int ty0 = blockIdx.x * CH;
    int tid = threadIdx.x;
    if (tid == 0) s_cnt = 0;
    __syncthreads();

    const float4* hb4 = reinterpret_cast<const float4*>(h + (size_t)b*HW);
    float4*       ob4 = reinterpret_cast<float4*>(out + OFF_HEAT + (size_t)b*HW);
    int xb = tid * 4;

    float4 zero4 = make_float4(0.f, 0.f, 0.f, 0.f);
    float4 w0=zero4,w1=zero4,w2=zero4,w3=zero4,w4=zero4,w5=zero4,w6=zero4;
    float4 d0=zero4,d1=zero4,d2=zero4;

    #pragma unroll
    for (int t = 0; t < CH + 6; ++t) {
        int yy = ty0 - 3 + t;
        float4 qm = zero4, qc = zero4, qp = zero4;
        if (yy >= 0 && yy < HH) {
            int rb = yy * (WW/4);
            qc = __ldg(hb4 + rb + tid);
            if (tid > 0)      qm = __ldg(hb4 + rb + tid - 1);
            if (tid < NT - 1) qp = __ldg(hb4 + rb + tid + 1);
            if (t >= 3 && t < CH + 3) ob4[rb + tid] = qc;
        }
        float p1 = fmaxf(qm.y, qm.z);
        float p2 = fmaxf(qm.z, qm.w);
        float p3 = fmaxf(qm.w, qc.x);
        float p4 = fmaxf(qc.x, qc.y);
        float p5 = fmaxf(qc.y, qc.z);
        float p6 = fmaxf(qc.z, qc.w);
        float p7 = fmaxf(qc.w, qp.x);
        float p8 = fmaxf(qp.x, qp.y);
        float4 rm;
        rm.x = fmaxf(fmaxf(p1, p3), fmaxf(p5, qc.w));
        rm.y = fmaxf(fmaxf(p2, p4), fmaxf(p6, qp.x));
        rm.z = fmaxf(fmaxf(p3, p5), fmaxf(p7, qp.y));
        rm.w = fmaxf(fmaxf(p4, p6), fmaxf(p8, qp.z));

        float4 vcand = d0;
        d0 = d1; d1 = d2; d2 = qc;
        w0 = w1; w1 = w2; w2 = w3; w3 = w4; w4 = w5; w5 = w6; w6 = rm;

        if (t >= 6) {
            int yc = yy - 3;
            if (yc >= 4 && yc < HH - 4) {
                float4 m;
                m.x = fmaxf(fmaxf(fmaxf(w0.x,w1.x),fmaxf(w2.x,w3.x)),
                            fmaxf(fmaxf(w4.x,w5.x),w6.x));
                m.y = fmaxf(fmaxf(fmaxf(w0.y,w1.y),fmaxf(w2.y,w3.y)),
                            fmaxf(fmaxf(w4.y,w5.y),w6.y));
                m.z = fmaxf(fmaxf(fmaxf(w0.z,w1.z),fmaxf(w2.z,w3.z)),
                            fmaxf(fmaxf(w4.z,w5.z),w6.z));
                m.w = fmaxf(fmaxf(fmaxf(w0.w,w1.w),fmaxf(w2.w,w3.w)),
                            fmaxf(fmaxf(w4.w,w5.w),w6.w));
                float vj[4] = {vcand.x, vcand.y, vcand.z, vcand.w};
                float mj[4] = {m.x, m.y, m.z, m.w};
                #pragma unroll
                for (int j = 0; j < 4; ++j) {
                    int x = xb + j;
                    if (x >= 4 && x < WW-4 && vj[j] > 0.f && vj[j] >= mj[j]) {
                        int p = atomicAdd(&s_cnt, 1);
                        if (p < SBUF) {
                            s_val[p] = 0xFFFFFFFFu - __float_as_uint(vj[j]);
                            s_idx[p] = (unsigned)(yc*WW + x);
                        }
                    }
                }
            }
        }
    }

    __syncthreads();
    int cnt = s_cnt; if (cnt > SBUF) cnt = SBUF;
    if (tid == 0) s_base = atomicAdd(&g_count[b], cnt);
    __syncthreads();
    int base = s_base;
    for (int i = tid; i < cnt; i += NT) {
        int slot = base + i;
        if (slot < CAND_CAP) {
            g_cval[b*CAND_CAP + slot] = s_val[i];
            g_cidx[b*CAND_CAP + slot] = s_idx[i];
        }
    }
}

// exact per-batch top-K (proven): one 2048-bin histogram; direct gather when
// the coarse set fits 512, else one refine pass. Bitonic sort.
__global__ __launch_bounds__(1024) void k_select(float* __restrict__ out) {
    __shared__ unsigned int bins[2048];
    __shared__ int s_warp[32];
    __shared__ unsigned int s_bin;
    __shared__ int s_newrank;
    __shared__ int s_fits;
    __shared__ unsigned long long s_keys[512];
    __shared__ int s_cnt;

    int b = blockIdx.x;
    int tid = threadIdx.x;
    int lane = tid & 31, wid = tid >> 5;
    int n = g_count[b]; if (n > CAND_CAP) n = CAND_CAP;
    const unsigned int* vals = g_cval + (size_t)b*CAND_CAP;
    const unsigned int* idxs = g_cidx + (size_t)b*CAND_CAP;

    int nIter = (n + 1023) >> 10;
    int gshift = 21;
    unsigned int gpiv = 2047u;
    int rank = KK;

    if (n >= KK) {
        for (int i = tid; i < 2048; i += 1024) bins[i] = 0;
        __syncthreads();
        for (int it = 0; it < nIter; ++it) {
            int i = (it << 10) + tid;
            bool active = (i < n);
            unsigned int vk = active ? vals[i] : 0u;
            unsigned int bin = vk >> 21;
            unsigned int m = __ballot_sync(0xFFFFFFFFu, active);
            if (active) {
                unsigned int peers = __match_any_sync(m, bin);
                int ldr = __ffs(peers) - 1;
                if (lane == ldr) atomicAdd(&bins[bin], (unsigned)__popc(peers));
            }
        }
        __syncthreads();
        {
            int c0 = (int)bins[2*tid];
            int c1 = (int)bins[2*tid + 1];
            int s = c0 + c1;
            int v2 = s;
            #pragma unroll
            for (int o = 1; o < 32; o <<= 1) {
                int t = __shfl_up_sync(0xFFFFFFFFu, v2, o);
                if (lane >= o) v2 += t;
            }
            if (lane == 31) s_warp[wid] = v2;
            __syncthreads();
            if (wid == 0) {
                int ws = s_warp[lane];
                #pragma unroll
                for (int o = 1; o < 32; o <<= 1) {
                    int t = __shfl_up_sync(0xFFFFFFFFu, ws, o);
                    if (lane >= o) ws += t;
                }
                s_warp[lane] = ws;
            }
            __syncthreads();
            int incl = v2 + (wid > 0 ? s_warp[wid - 1] : 0);
            int excl = incl - s;
            if (rank > excl && rank <= excl + c0) {
                s_bin = (unsigned)(2*tid);
                s_newrank = rank - excl;
                s_fits = (excl + c0 <= 512);
            } else if (rank > excl + c0 && rank <= incl) {
                s_bin = (unsigned)(2*tid + 1);
                s_newrank = rank - excl - c0;
                s_fits = (excl + c0 + c1 <= 512);
            }
            __syncthreads();
        }
        unsigned int coarse = s_bin;
        rank = s_newrank;
        int fits = s_fits;
        __syncthreads();

        if (fits) {
            gshift = 21; gpiv = coarse;
        } else {
            for (int i = tid; i < 2048; i += 1024) bins[i] = 0;
            __syncthreads();
            for (int it = 0; it < nIter; ++it) {
                int i = (it << 10) + tid;
                bool active = (i < n);
                unsigned int vk = active ? vals[i] : 0u;
                bool ok = active && ((vk >> 21) == coarse);
                unsigned int bin = (vk >> 10) & 2047u;
                unsigned int m = __ballot_sync(0xFFFFFFFFu, ok);
                if (ok) {
                    unsigned int peers = __match_any_sync(m, bin);
                    int ldr = __ffs(peers) - 1;
                    if (lane == ldr) atomicAdd(&bins[bin], (unsigned)__popc(peers));
                }
            }
            __syncthreads();
            {
                int d0 = (int)bins[2*tid];
                int d1 = (int)bins[2*tid + 1];
                int ss = d0 + d1;
                int vv2 = ss;
                #pragma unroll
                for (int o = 1; o < 32; o <<= 1) {
                    int t = __shfl_up_sync(0xFFFFFFFFu, vv2, o);
                    if (lane >= o) vv2 += t;
                }
                if (lane == 31) s_warp[wid] = vv2;
                __syncthreads();
                if (wid == 0) {
                    int ws = s_warp[lane];
                    #pragma unroll
                    for (int o = 1; o < 32; o <<= 1) {
                        int t = __shfl_up_sync(0xFFFFFFFFu, ws, o);
                        if (lane >= o) ws += t;
                    }
                    s_warp[lane] = ws;
                }
                __syncthreads();
                int incl2 = vv2 + (wid > 0 ? s_warp[wid - 1] : 0);
                int excl2 = incl2 - ss;
                if (rank > excl2 && rank <= excl2 + d0)
                    s_bin = (unsigned)(2*tid);
                else if (rank > excl2 + d0 && rank <= incl2)
                    s_bin = (unsigned)(2*tid + 1);
                __syncthreads();
            }
            gshift = 10; gpiv = (coarse << 11) | s_bin;
            __syncthreads();
        }
    }

    if (tid == 0) s_cnt = 0;
    __syncthreads();
    for (int it = 0; it < nIter; ++it) {
        int i = (it << 10) + tid;
        bool active = (i < n);
        unsigned int vk = active ? vals[i] : 0xFFFFFFFFu;
        bool take = active && ((vk >> gshift) <= gpiv);
        unsigned int m = __ballot_sync(0xFFFFFFFFu, take);
        if (take) {
            int ldr = __ffs(m) - 1;
            int base;
            if (lane == ldr) base = atomicAdd(&s_cnt, __popc(m));
            base = __shfl_sync(m, base, ldr);
            int slot = base + __popc(m & ((1u << lane) - 1u));
            if (slot < 512)
                s_keys[slot] = ((unsigned long long)vk << 32) | idxs[i];
        }
    }
    __syncthreads();
    int cnt = s_cnt; if (cnt > 512) cnt = 512;
    for (int i = tid; i < 512; i += 1024)
        if (i >= cnt) s_keys[i] = ~0ULL;
    __syncthreads();

    for (unsigned kk2 = 2; kk2 <= 512; kk2 <<= 1) {
        for (unsigned j = kk2 >> 1; j > 0; j >>= 1) {
            for (unsigned i = tid; i < 512; i += 1024) {
                unsigned ixj = i ^ j;
                if (ixj > i) {
                    bool asc = ((i & kk2) == 0);
                    unsigned long long a = s_keys[i], c = s_keys[ixj];
                    if ((a > c) == asc) { s_keys[i] = c; s_keys[ixj] = a; }
                }
            }
            __syncthreads();
        }
    }

    for (int k = tid; k < KK; k += 1024) {
        unsigned long long key = s_keys[k];
        unsigned int vb = 0xFFFFFFFFu - (unsigned int)(key >> 32);
        int idx = (int)(unsigned int)(key & 0xFFFFFFFFu);
        int y = idx / WW;
        int x = idx - y*WW;
        out[OFF_KPTS + ((size_t)b*KK + k)*2 + 0] = (float)x + 0.5f;
        out[OFF_KPTS + ((size_t)b*KK + k)*2 + 1] = (float)y + 0.5f;
        out[OFF_SCORES + (size_t)b*KK + k] = __uint_as_float(vb);
        g_topidx[b*KK + k] = idx;
    }

    if (tid == 0) g_count[b] = 0;
}

// Phase A: channel-resident sampling (no atomics). One block per (channel, batch).
__global__ __launch_bounds__(256) void k_gather(const float* __restrict__ desc,
                                                float* __restrict__ out) {
    __shared__ float s_ch[HCC*WCC];   // 4800 floats = 19200 B

    int c = blockIdx.x;
    int b = blockIdx.y;
    int tid = threadIdx.x;

    const float4* dp4 = reinterpret_cast<const float4*>(
        desc + ((size_t)b*CC + c) * (HCC*WCC));
    float4* s4 = reinterpret_cast<float4*>(s_ch);
    #pragma unroll
    for (int i = tid; i < (HCC*WCC)/4; i += 256)   // 1200 float4
        s4[i] = __ldg(dp4 + i);
    __syncthreads();

    float* orow = out + OFF_SAMPLED + ((size_t)b*CC + c) * KK;
    const int* tix = g_topidx + b*KK;

    for (int k = tid; k < KK; k += 256) {
        int idx = __ldg(tix + k);
        int iy = idx / WW;
        int ix = idx - iy*WW;
        float kx = (float)ix + 0.5f;
        float ky = (float)iy + 0.5f;
        float ux = (kx - 3.5f) / 635.5f;
        float uy = (ky - 3.5f) / 475.5f;
        float gx = ((ux * 2.f - 1.f) + 1.f) * 0.5f * (float)(WCC - 1);
        float gy = ((uy * 2.f - 1.f) + 1.f) * 0.5f * (float)(HCC - 1);
        float x0f = floorf(gx), y0f = floorf(gy);
        float wx = gx - x0f, wy = gy - y0f;
        int x0 = (int)x0f;
        int y0 = (int)y0f;
        int o0 = y0*WCC + x0;
        int o1 = o0 + WCC;
        float d00 = s_ch[o0],     d01 = s_ch[o0 + 1];
        float d10 = s_ch[o1],     d11 = s_ch[o1 + 1];
        float v = d00*(1.f-wx)*(1.f-wy) + d01*wx*(1.f-wy)
                + d10*(1.f-wx)*wy       + d11*wx*wy;
        orow[k] = v;
    }
}

// Phase B: tiled norm + scale in one pass. grid (NKT, BB), block 256.
// Tile = 16 kpts x 256 channels (16KB smem); consecutive k contiguous in the
// output layout -> fully sector-efficient float4 loads/stores; norms via
// in-smem channel reduction (no atomics).
__global__ __launch_bounds__(256) void k_normscale(float* __restrict__ out) {
    __shared__ float s_t[CC*KT];      // [c][kk] 16384 B
    __shared__ float s_p[16][KT];
    __shared__ float s_inv[KT];

    int b  = blockIdx.y;
    int k0 = blockIdx.x * KT;
    int tid = threadIdx.x;
    float* base = out + OFF_SAMPLED + (size_t)b*CC*KK + k0;

    // load: 1024 float4 (4 per thread), coalesced within 64B channel rows
    #pragma unroll
    for (int r = 0; r < 4; ++r) {
        int i = tid + 256*r;
        int c = i >> 2, q = i & 3;
        float4 v = *reinterpret_cast<const float4*>(base + c*KK + q*4);
        *reinterpret_cast<float4*>(&s_t[c*KT + q*4]) = v;
    }
    __syncthreads();

    // per-kpt sum of squares over 256 channels: 16 groups x 16 kk
    int kk = tid & 15, grp = tid >> 4;
    float s = 0.f;
    #pragma unroll
    for (int j = 0; j < 16; ++j) {
        float v = s_t[(grp*16 + j)*KT + kk];
        s += v*v;
    }
    s_p[grp][kk] = s;
    __syncthreads();
    if (tid < KT) {
        float t = 0.f;
        #pragma unroll
        for (int g = 0; g < 16; ++g) t += s_p[g][tid];
        s_inv[tid] = 1.0f / sqrtf(t + 1e-12f);
    }
    __syncthreads();

    // scale + write back
    #pragma unroll
    for (int r = 0; r < 4; ++r) {
        int i = tid + 256*r;
        int c = i >> 2, q = i & 3;
        float4 v = *reinterpret_cast<float4*>(&s_t[c*KT + q*4]);
        v.x *= s_inv[q*4 + 0];
        v.y *= s_inv[q*4 + 1];
        v.z *= s_inv[q*4 + 2];
        v.w *= s_inv[q*4 + 3];
        *reinterpret_cast<float4*>(base + c*KK + q*4) = v;
    }
}

extern "C" void kernel_launch(void* const* d_in, const int* in_sizes, int n_in,
                              void* d_out, int out_size) {
    const float* heat = (const float*)d_in[0];
    const float* desc = (const float*)d_in[1];
    float* out = (float*)d_out;

    dim3 ngrid(NBY, BB);
    k_nms<<<ngrid, NT>>>(heat, out);

    k_select<<<BB, 1024>>>(out);

    dim3 ggrid(CC, BB);
    k_gather<<<ggrid, 256>>>(desc, out);

    dim3 nsgrid(NKT, BB);
    k_normscale<<<nsgrid, 256>>>(out);
}